// round 7
// baseline (speedup 1.0000x reference)
#include <cuda_runtime.h>
#include <math.h>

#define BB 4
#define NN 8192
#define MM 8192
#define FEAT 64
#define KNN 16
#define K4 4
#define EPS 1e-5f
#define QPB 16     // queries per mlp block
#define BINS 32768 // 15-bit morton (5 bits/dim)
#define NTILE 128  // point tiles of 64
#define KNN_SMEM ((MM + 2 * NTILE) * 16 + MM * 4)

// ---------------- scratch (static device globals; no runtime alloc) ----------------
__device__ float g_w0f[FEAT * 3];
__device__ float g_b0f[FEAT];
__device__ float g_w1t[FEAT * FEAT];
__device__ float g_b1f[FEAT];
__device__ int   g_knn[BB * NN * KNN];
__device__ float g_lft[BB * MM * FEAT];   // local_feat transposed to (B, M, FEAT)
// query sort
__device__ int   g_hist[BB][BINS];
__device__ int   g_base[BB][BINS];
__device__ unsigned short g_key[BB][NN];
__device__ int   g_perm[BB][NN];          // sorted pos -> original n
__device__ float g_qs[BB][3][NN];
// point sort
__device__ int   g_ohist[BB][BINS];
__device__ int   g_obase[BB][BINS];
__device__ unsigned short g_okey[BB][MM];
__device__ int   g_operm[BB][MM];         // sorted pos -> original m
__device__ float4 g_opts[BB][MM];         // sorted (x,y,z,o2)

// ---------------- kernel 0: fold BN into conv weights + zero histograms ----------------
__global__ void fold_kernel(const float* __restrict__ w0, const float* __restrict__ b0,
                            const float* __restrict__ g0, const float* __restrict__ be0,
                            const float* __restrict__ m0, const float* __restrict__ v0,
                            const float* __restrict__ w1, const float* __restrict__ b1,
                            const float* __restrict__ g1, const float* __restrict__ be1,
                            const float* __restrict__ m1, const float* __restrict__ v1) {
    int tid = threadIdx.x + blockIdx.x * blockDim.x;
    if (blockIdx.x == 0) {
        if (tid < FEAT) {
            float inv0 = g0[tid] / sqrtf(v0[tid] + EPS);
            g_w0f[tid * 3 + 0] = w0[tid * 3 + 0] * inv0;
            g_w0f[tid * 3 + 1] = w0[tid * 3 + 1] * inv0;
            g_w0f[tid * 3 + 2] = w0[tid * 3 + 2] * inv0;
            g_b0f[tid] = (b0[tid] - m0[tid]) * inv0 + be0[tid];
            float inv1 = g1[tid] / sqrtf(v1[tid] + EPS);
            g_b1f[tid] = (b1[tid] - m1[tid]) * inv1 + be1[tid];
        }
        for (int i = threadIdx.x; i < FEAT * FEAT; i += blockDim.x) {
            int cout = i / FEAT, cin = i % FEAT;
            float inv1 = g1[cout] / sqrtf(v1[cout] + EPS);
            g_w1t[cin * FEAT + cout] = w1[cout * FEAT + cin] * inv1;
        }
    }
    int total = BB * BINS;
    for (int i = tid; i < total; i += blockDim.x * gridDim.x) {
        (&g_hist[0][0])[i] = 0;
        (&g_ohist[0][0])[i] = 0;
    }
}

// ---------------- morton helpers ----------------
__device__ __forceinline__ int spread5(int v) {
    return (v & 1) | ((v & 2) << 2) | ((v & 4) << 4) | ((v & 8) << 6) | ((v & 16) << 8);
}
__device__ __forceinline__ int morton_key(float x, float y, float z) {
    int ux = min(31, max(0, (int)((x + 4.0f) * 4.0f)));
    int uy = min(31, max(0, (int)((y + 4.0f) * 4.0f)));
    int uz = min(31, max(0, (int)((z + 4.0f) * 4.0f)));
    return spread5(ux) | (spread5(uy) << 1) | (spread5(uz) << 2);
}

// ---------------- query sort ----------------
__global__ void __launch_bounds__(256) key_kernel(const float* __restrict__ q) {
    int b = blockIdx.y;
    int n = blockIdx.x * 256 + threadIdx.x;
    float x = q[((size_t)(b * 3 + 0)) * NN + n];
    float y = q[((size_t)(b * 3 + 1)) * NN + n];
    float z = q[((size_t)(b * 3 + 2)) * NN + n];
    int key = morton_key(x, y, z);
    g_key[b][n] = (unsigned short)key;
    atomicAdd(&g_hist[b][key], 1);
}

__global__ void __launch_bounds__(1024) scan_kernel(int which) {
    __shared__ int ps[1024];
    int b = blockIdx.x;
    int t = threadIdx.x;
    int (*hist)[BINS] = which ? g_ohist : g_hist;
    int (*base)[BINS] = which ? g_obase : g_base;
    int s = 0;
#pragma unroll
    for (int i = 0; i < BINS / 1024; i++) s += hist[b][t * (BINS / 1024) + i];
    ps[t] = s;
    __syncthreads();
    for (int off = 1; off < 1024; off <<= 1) {
        int v = (t >= off) ? ps[t - off] : 0;
        __syncthreads();
        ps[t] += v;
        __syncthreads();
    }
    int run = ps[t] - s;
#pragma unroll
    for (int i = 0; i < BINS / 1024; i++) {
        int bin = t * (BINS / 1024) + i;
        base[b][bin] = run;
        run += hist[b][bin];
    }
}

__global__ void __launch_bounds__(256) scatter_kernel(const float* __restrict__ q) {
    int b = blockIdx.y;
    int n = blockIdx.x * 256 + threadIdx.x;
    int key = g_key[b][n];
    int pos = atomicAdd(&g_base[b][key], 1);
    g_perm[b][pos] = n;
    g_qs[b][0][pos] = q[((size_t)(b * 3 + 0)) * NN + n];
    g_qs[b][1][pos] = q[((size_t)(b * 3 + 1)) * NN + n];
    g_qs[b][2][pos] = q[((size_t)(b * 3 + 2)) * NN + n];
}

// ---------------- point sort ----------------
__global__ void __launch_bounds__(256) key_o_kernel(const float* __restrict__ o) {
    int b = blockIdx.y;
    int m = blockIdx.x * 256 + threadIdx.x;
    float x = o[((size_t)(b * 3 + 0)) * MM + m];
    float y = o[((size_t)(b * 3 + 1)) * MM + m];
    float z = o[((size_t)(b * 3 + 2)) * MM + m];
    int key = morton_key(x, y, z);
    g_okey[b][m] = (unsigned short)key;
    atomicAdd(&g_ohist[b][key], 1);
}

__global__ void __launch_bounds__(256) scatter_o_kernel(const float* __restrict__ o) {
    int b = blockIdx.y;
    int m = blockIdx.x * 256 + threadIdx.x;
    int key = g_okey[b][m];
    int pos = atomicAdd(&g_obase[b][key], 1);
    g_operm[b][pos] = m;
    float x = o[((size_t)(b * 3 + 0)) * MM + m];
    float y = o[((size_t)(b * 3 + 1)) * MM + m];
    float z = o[((size_t)(b * 3 + 2)) * MM + m];
    // reference rounding: o2 = (x*x + y*y) + z*z
    float o2 = __fadd_rn(__fadd_rn(__fmul_rn(x, x), __fmul_rn(y, y)), __fmul_rn(z, z));
    g_opts[b][pos] = make_float4(x, y, z, o2);
}

// ---------------- kernel 1: transpose local_feat (B,64,M) -> (B,M,64) ----------------
__global__ void __launch_bounds__(256) transpose_kernel(const float* __restrict__ lf) {
    __shared__ float tile[64][65];
    int b = blockIdx.y;
    int m0 = blockIdx.x * 64;
    int tid = threadIdx.x;
#pragma unroll
    for (int r = 0; r < 16; r++) {
        int c  = (tid >> 6) + (r << 2);
        int mm = tid & 63;
        tile[c][mm] = lf[((size_t)(b * FEAT + c)) * MM + m0 + mm];
    }
    __syncthreads();
#pragma unroll
    for (int r = 0; r < 16; r++) {
        int mm = (tid >> 6) + (r << 2);
        int c  = tid & 63;
        g_lft[((size_t)(b * MM + m0 + mm)) * FEAT + c] = tile[c][mm];
    }
}

// ---------------- kernel 2: fused KNN with AABB tile pruning ----------------
__device__ __forceinline__ float dist_key(float qx, float qy, float qz, float q2,
                                          const float4& o) {
    float cross = __fmaf_rn(o.z, qz, __fmaf_rn(o.y, qy, __fmul_rn(o.x, qx)));
    return __fsub_rn(__fadd_rn(q2, o.w), __fmul_rn(2.0f, cross));
}

// Lexicographic (value, original-index) insertion: matches jax.lax.top_k's
// stable ordering (ascending value, ties -> lowest original index), making the
// result independent of point scan order.
__device__ __forceinline__ void topk_insert(float (&d)[KNN], int (&di)[KNN], float sv, int om) {
    if (sv < d[KNN - 1] || (sv == d[KNN - 1] && om < di[KNN - 1])) {
#pragma unroll
        for (int jj = KNN - 1; jj > 0; --jj) {
            bool sh = sv < d[jj - 1] || (sv == d[jj - 1] && om < di[jj - 1]);
            bool he = (sv < d[jj] || (sv == d[jj] && om < di[jj])) && !sh;
            float nd = sh ? d[jj - 1] : (he ? sv : d[jj]);
            int   ni = sh ? di[jj - 1] : (he ? om : di[jj]);
            d[jj] = nd;
            di[jj] = ni;
        }
        if (sv < d[0] || (sv == d[0] && om < di[0])) { d[0] = sv; di[0] = om; }
    }
}

__global__ void __launch_bounds__(256) knn_kernel() {
    extern __shared__ float4 sm[];
    float4* pts = sm;                       // MM points (x,y,z,o2)
    float4* bbx = sm + MM;                  // NTILE tiles: [2t]=min, [2t+1]=max
    int* smop = (int*)(sm + MM + 2 * NTILE); // sorted pos -> original m
    int b = blockIdx.y;
    int tid = threadIdx.x;

    for (int i = tid; i < MM; i += 256) {
        pts[i] = g_opts[b][i];
        smop[i] = g_operm[b][i];
    }
    __syncthreads();
    if (tid < NTILE) {
        int pb = tid << 6;
        float4 p = pts[pb];
        float mnx = p.x, mxx = p.x, mny = p.y, mxy = p.y, mnz = p.z, mxz = p.z;
        for (int j = 1; j < 64; j++) {
            float4 q = pts[pb + j];
            mnx = fminf(mnx, q.x); mxx = fmaxf(mxx, q.x);
            mny = fminf(mny, q.y); mxy = fmaxf(mxy, q.y);
            mnz = fminf(mnz, q.z); mxz = fmaxf(mxz, q.z);
        }
        bbx[2 * tid]     = make_float4(mnx, mny, mnz, 0.f);
        bbx[2 * tid + 1] = make_float4(mxx, mxy, mxz, 0.f);
    }

    int n = blockIdx.x * 256 + tid;  // sorted query position
    float qx = g_qs[b][0][n];
    float qy = g_qs[b][1][n];
    float qz = g_qs[b][2][n];
    float q2 = __fadd_rn(__fadd_rn(__fmul_rn(qx, qx), __fmul_rn(qy, qy)), __fmul_rn(qz, qz));
    __syncthreads();

    // warp bounding box of queries
    float wnx = qx, wxx = qx, wny = qy, wxy = qy, wnz = qz, wxz = qz;
#pragma unroll
    for (int off = 16; off; off >>= 1) {
        wnx = fminf(wnx, __shfl_xor_sync(0xffffffffu, wnx, off));
        wxx = fmaxf(wxx, __shfl_xor_sync(0xffffffffu, wxx, off));
        wny = fminf(wny, __shfl_xor_sync(0xffffffffu, wny, off));
        wxy = fmaxf(wxy, __shfl_xor_sync(0xffffffffu, wxy, off));
        wnz = fminf(wnz, __shfl_xor_sync(0xffffffffu, wnz, off));
        wxz = fmaxf(wxz, __shfl_xor_sync(0xffffffffu, wxz, off));
    }

    float d[KNN];
    int   di[KNN];
#pragma unroll
    for (int j = 0; j < KNN; j++) { d[j] = 3.0e38f; di[j] = 0x7fffffff; }

    // home tile: queries at sorted fraction f sit near points at fraction f
    int home = (blockIdx.x * 256 + (tid & ~31)) >> 6;

    for (int i = 0; i < NTILE; i++) {
        int t = (home + i) & (NTILE - 1);
        // warp-max threshold (identical across lanes)
        float thr = d[KNN - 1];
#pragma unroll
        for (int off = 16; off; off >>= 1)
            thr = fmaxf(thr, __shfl_xor_sync(0xffffffffu, thr, off));
        float4 tmn = bbx[2 * t];
        float4 tmx = bbx[2 * t + 1];
        float gx = fmaxf(0.f, fmaxf(tmn.x - wxx, wnx - tmx.x));
        float gy = fmaxf(0.f, fmaxf(tmn.y - wxy, wny - tmx.y));
        float gz = fmaxf(0.f, fmaxf(tmn.z - wxz, wnz - tmx.z));
        float mind2 = gx * gx + gy * gy + gz * gz;
        if (mind2 > thr + 1e-3f) continue;  // margin >> dist_key rounding slack

        int pb = t << 6;
        for (int j = 0; j < 64; j += 4) {
            float4 o0 = pts[pb + j + 0];
            float4 o1 = pts[pb + j + 1];
            float4 o2 = pts[pb + j + 2];
            float4 o3 = pts[pb + j + 3];
            float s0 = dist_key(qx, qy, qz, q2, o0);
            float s1 = dist_key(qx, qy, qz, q2, o1);
            float s2 = dist_key(qx, qy, qz, q2, o2);
            float s3 = dist_key(qx, qy, qz, q2, o3);
            float mn = fminf(fminf(s0, s1), fminf(s2, s3));
            // votes use <= so equal-value (tie) candidates still enter the
            // lexicographic insert, which decides by original index
            if (__any_sync(0xffffffffu, mn <= d[KNN - 1])) {
                if (__any_sync(0xffffffffu, s0 <= d[KNN - 1])) topk_insert(d, di, s0, smop[pb + j + 0]);
                if (__any_sync(0xffffffffu, s1 <= d[KNN - 1])) topk_insert(d, di, s1, smop[pb + j + 1]);
                if (__any_sync(0xffffffffu, s2 <= d[KNN - 1])) topk_insert(d, di, s2, smop[pb + j + 2]);
                if (__any_sync(0xffffffffu, s3 <= d[KNN - 1])) topk_insert(d, di, s3, smop[pb + j + 3]);
            }
        }
    }

    int orign = g_perm[b][n];
    int outb = ((b * NN) + orign) * KNN;
#pragma unroll
    for (int j = 0; j < KNN; j++) g_knn[outb + j] = di[j];
}

// ---------------- kernel 3: fused MLP + gather + blend (QPB queries/block) ----------------
__global__ void __launch_bounds__(256) mlp_kernel(const float* __restrict__ orig,
                                                  const float* __restrict__ query,
                                                  const float* __restrict__ w2,
                                                  const float* __restrict__ b2,
                                                  float* __restrict__ out) {
    __shared__ float  w1s[FEAT * FEAT];
    __shared__ float  f0s[4][FEAT * K4];
    __shared__ float4 rel4[4][KNN];
    __shared__ int    idxs[4][KNN];
    __shared__ float  red[4][2][8];
    __shared__ float  outs[4][FEAT];

    int tid = threadIdx.x;
    int g = tid >> 6;
    int c = tid & 63;
    int b = blockIdx.y;

    for (int i = tid; i < FEAT * FEAT; i += 256) w1s[i] = g_w1t[i];

    float w00 = g_w0f[c * 3 + 0], w01 = g_w0f[c * 3 + 1], w02 = g_w0f[c * 3 + 2];
    float bb0 = g_b0f[c];
    float bb1 = g_b1f[c];
    float w2a = w2[c], w2b = w2[FEAT + c];
    float b2v = b2[0];

    for (int it = 0; it < QPB / 4; ++it) {
        int n = blockIdx.x * QPB + it * 4 + g;

        if (c < KNN) idxs[g][c] = g_knn[(((size_t)b * NN) + n) * KNN + c];
        __syncthreads();

        float p0 = g_lft[(((size_t)b * MM) + idxs[g][0]) * FEAT + c];
        float p1 = g_lft[(((size_t)b * MM) + idxs[g][1]) * FEAT + c];
        float p2 = g_lft[(((size_t)b * MM) + idxs[g][2]) * FEAT + c];
        float p3 = g_lft[(((size_t)b * MM) + idxs[g][3]) * FEAT + c];

        if (c < 48) {
            int j = c / 3;
            int a = c - j * 3;
            int m = idxs[g][j];
            float qa = query[((size_t)(b * 3 + a)) * NN + n];
            ((float*)&rel4[g][j])[a] = orig[((size_t)(b * 3 + a)) * MM + m] - qa;
        }
        __syncthreads();

        float fg = 0.f;
        float f0k0 = 0.f, f0k1 = 0.f, f0k2 = 0.f, f0k3 = 0.f;
#pragma unroll
        for (int j = 0; j < KNN; j++) {
            float4 r = rel4[g][j];
            float f = fmaf(w00, r.x, fmaf(w01, r.y, fmaf(w02, r.z, bb0)));
            f = fmaxf(f, 0.f);
            fg = fmaxf(fg, f);
            if (j == 0) f0k0 = f;
            if (j == 1) f0k1 = f;
            if (j == 2) f0k2 = f;
            if (j == 3) f0k3 = f;
        }
        *(float4*)&f0s[g][c * 4] = make_float4(f0k0, f0k1, f0k2, f0k3);
        __syncthreads();

        float a0 = bb1, a1 = bb1, a2 = bb1, a3 = bb1;
#pragma unroll 8
        for (int cin = 0; cin < FEAT; ++cin) {
            float wv = w1s[cin * FEAT + c];
            float4 f = *(float4*)&f0s[g][cin * 4];
            a0 = fmaf(wv, f.x, a0);
            a1 = fmaf(wv, f.y, a1);
            a2 = fmaf(wv, f.z, a2);
            a3 = fmaf(wv, f.w, a3);
        }
        float r0 = fmaxf(a0, 0.f), r1 = fmaxf(a1, 0.f), r2 = fmaxf(a2, 0.f), r3 = fmaxf(a3, 0.f);

        float t0 = w2a * r0, t1 = w2a * r1, t2 = w2a * r2, t3 = w2a * r3;
        float u = w2b * fg;
#pragma unroll
        for (int off = 16; off; off >>= 1) {
            t0 += __shfl_down_sync(0xffffffffu, t0, off);
            t1 += __shfl_down_sync(0xffffffffu, t1, off);
            t2 += __shfl_down_sync(0xffffffffu, t2, off);
            t3 += __shfl_down_sync(0xffffffffu, t3, off);
            u  += __shfl_down_sync(0xffffffffu, u, off);
        }
        if ((c & 31) == 0) {
            float* rr = red[g][c >> 5];
            rr[0] = t0; rr[1] = t1; rr[2] = t2; rr[3] = t3; rr[4] = u;
        }
        __syncthreads();

        float base = red[g][0][4] + red[g][1][4] + b2v;
        float z0 = red[g][0][0] + red[g][1][0] + base;
        float z1 = red[g][0][1] + red[g][1][1] + base;
        float z2 = red[g][0][2] + red[g][1][2] + base;
        float z3 = red[g][0][3] + red[g][1][3] + base;
        float wg0 = 1.f / (1.f + expf(-z0));
        float wg1 = 1.f / (1.f + expf(-z1));
        float wg2 = 1.f / (1.f + expf(-z2));
        float wg3 = 1.f / (1.f + expf(-z3));

        float o = (1.f - wg0) * r0 + wg0 * p0;
        o      += (1.f - wg1) * r1 + wg1 * p1;
        o      += (1.f - wg2) * r2 + wg2 * p2;
        o      += (1.f - wg3) * r3 + wg3 * p3;

        outs[g][c] = o;
        __syncthreads();

        int c2 = tid >> 2, g2 = tid & 3;
        out[((size_t)(b * FEAT + c2)) * NN + blockIdx.x * QPB + it * 4 + g2] = outs[g2][c2];
        __syncthreads();
    }
}

// ---------------- launch ----------------
extern "C" void kernel_launch(void* const* d_in, const int* in_sizes, int n_in,
                              void* d_out, int out_size) {
    const float* orig  = (const float*)d_in[0];
    const float* query = (const float*)d_in[1];
    const float* lf    = (const float*)d_in[2];
    const float* w0  = (const float*)d_in[3];
    const float* b0  = (const float*)d_in[4];
    const float* g0  = (const float*)d_in[5];
    const float* be0 = (const float*)d_in[6];
    const float* m0  = (const float*)d_in[7];
    const float* v0  = (const float*)d_in[8];
    const float* w1  = (const float*)d_in[9];
    const float* b1  = (const float*)d_in[10];
    const float* g1  = (const float*)d_in[11];
    const float* be1 = (const float*)d_in[12];
    const float* m1  = (const float*)d_in[13];
    const float* v1  = (const float*)d_in[14];
    const float* w2  = (const float*)d_in[15];
    const float* b2  = (const float*)d_in[16];
    float* out = (float*)d_out;

    cudaFuncSetAttribute(knn_kernel, cudaFuncAttributeMaxDynamicSharedMemorySize, KNN_SMEM);

    fold_kernel<<<8, 256>>>(w0, b0, g0, be0, m0, v0, w1, b1, g1, be1, m1, v1);
    key_kernel<<<dim3(NN / 256, BB), 256>>>(query);
    key_o_kernel<<<dim3(MM / 256, BB), 256>>>(orig);
    scan_kernel<<<BB, 1024>>>(0);
    scan_kernel<<<BB, 1024>>>(1);
    scatter_kernel<<<dim3(NN / 256, BB), 256>>>(query);
    scatter_o_kernel<<<dim3(MM / 256, BB), 256>>>(orig);
    transpose_kernel<<<dim3(MM / 64, BB), 256>>>(lf);
    knn_kernel<<<dim3(NN / 256, BB), 256, KNN_SMEM>>>();
    mlp_kernel<<<dim3(NN / QPB, BB), 256>>>(orig, query, w2, b2, out);
}

// round 8
// speedup vs baseline: 1.1896x; 1.1896x over previous
#include <cuda_runtime.h>
#include <math.h>

#define BB 4
#define NN 8192
#define MM 8192
#define FEAT 64
#define KNN 16
#define K4 4
#define EPS 1e-5f
#define QPB 16     // queries per mlp block
#define BINS 32768 // 15-bit morton (5 bits/dim)
#define NTILE 128  // 64-point subtiles per batch
#define SUPER 2048 // points per smem stage
#define SUBS 32    // subtiles per super

// ---------------- scratch (static device globals; no runtime alloc) ----------------
__device__ float g_w0f[FEAT * 3];
__device__ float g_b0f[FEAT];
__device__ float g_w1t[FEAT * FEAT];
__device__ float g_b1f[FEAT];
__device__ int   g_knn[BB * NN * KNN];
__device__ float g_lft[BB * MM * FEAT];   // local_feat transposed to (B, M, FEAT)
// query sort
__device__ int   g_hist[BB][BINS];
__device__ int   g_base[BB][BINS];
__device__ unsigned short g_key[BB][NN];
__device__ int   g_perm[BB][NN];          // sorted pos -> original n
__device__ float g_qs[BB][3][NN];
// point sort
__device__ int   g_ohist[BB][BINS];
__device__ int   g_obase[BB][BINS];
__device__ unsigned short g_okey[BB][MM];
__device__ int   g_operm[BB][MM];         // sorted pos -> original m
__device__ float4 g_opts[BB][MM];         // sorted (x,y,z,o2)
__device__ float4 g_bbx[BB][NTILE][2];    // per-subtile AABB (min,max)

// ---------------- kernel 0: fold BN into conv weights + zero histograms ----------------
__global__ void fold_kernel(const float* __restrict__ w0, const float* __restrict__ b0,
                            const float* __restrict__ g0, const float* __restrict__ be0,
                            const float* __restrict__ m0, const float* __restrict__ v0,
                            const float* __restrict__ w1, const float* __restrict__ b1,
                            const float* __restrict__ g1, const float* __restrict__ be1,
                            const float* __restrict__ m1, const float* __restrict__ v1) {
    int tid = threadIdx.x + blockIdx.x * blockDim.x;
    if (blockIdx.x == 0) {
        if (tid < FEAT) {
            float inv0 = g0[tid] / sqrtf(v0[tid] + EPS);
            g_w0f[tid * 3 + 0] = w0[tid * 3 + 0] * inv0;
            g_w0f[tid * 3 + 1] = w0[tid * 3 + 1] * inv0;
            g_w0f[tid * 3 + 2] = w0[tid * 3 + 2] * inv0;
            g_b0f[tid] = (b0[tid] - m0[tid]) * inv0 + be0[tid];
            float inv1 = g1[tid] / sqrtf(v1[tid] + EPS);
            g_b1f[tid] = (b1[tid] - m1[tid]) * inv1 + be1[tid];
        }
        for (int i = threadIdx.x; i < FEAT * FEAT; i += blockDim.x) {
            int cout = i / FEAT, cin = i % FEAT;
            float inv1 = g1[cout] / sqrtf(v1[cout] + EPS);
            g_w1t[cin * FEAT + cout] = w1[cout * FEAT + cin] * inv1;
        }
    }
    int total = BB * BINS;
    for (int i = tid; i < total; i += blockDim.x * gridDim.x) {
        (&g_hist[0][0])[i] = 0;
        (&g_ohist[0][0])[i] = 0;
    }
}

// ---------------- morton helpers ----------------
__device__ __forceinline__ int spread5(int v) {
    return (v & 1) | ((v & 2) << 2) | ((v & 4) << 4) | ((v & 8) << 6) | ((v & 16) << 8);
}
__device__ __forceinline__ int morton_key(float x, float y, float z) {
    int ux = min(31, max(0, (int)((x + 4.0f) * 4.0f)));
    int uy = min(31, max(0, (int)((y + 4.0f) * 4.0f)));
    int uz = min(31, max(0, (int)((z + 4.0f) * 4.0f)));
    return spread5(ux) | (spread5(uy) << 1) | (spread5(uz) << 2);
}

// ---------------- sort: keys ----------------
__global__ void __launch_bounds__(256) key_kernel(const float* __restrict__ q) {
    int b = blockIdx.y;
    int n = blockIdx.x * 256 + threadIdx.x;
    float x = q[((size_t)(b * 3 + 0)) * NN + n];
    float y = q[((size_t)(b * 3 + 1)) * NN + n];
    float z = q[((size_t)(b * 3 + 2)) * NN + n];
    int key = morton_key(x, y, z);
    g_key[b][n] = (unsigned short)key;
    atomicAdd(&g_hist[b][key], 1);
}

__global__ void __launch_bounds__(256) key_o_kernel(const float* __restrict__ o) {
    int b = blockIdx.y;
    int m = blockIdx.x * 256 + threadIdx.x;
    float x = o[((size_t)(b * 3 + 0)) * MM + m];
    float y = o[((size_t)(b * 3 + 1)) * MM + m];
    float z = o[((size_t)(b * 3 + 2)) * MM + m];
    int key = morton_key(x, y, z);
    g_okey[b][m] = (unsigned short)key;
    atomicAdd(&g_ohist[b][key], 1);
}

// ---------------- sort: fast hierarchical scan (both hists; grid (BB,2)) ----------------
__global__ void __launch_bounds__(1024) scan_kernel() {
    __shared__ int wsum[32];
    int b = blockIdx.x;
    int which = blockIdx.y;
    int (*hist)[BINS] = which ? g_ohist : g_hist;
    int (*base)[BINS] = which ? g_obase : g_base;
    int t = threadIdx.x;
    int lane = t & 31;
    int wid = t >> 5;
    int local[BINS / 1024];
    int s = 0;
#pragma unroll
    for (int i = 0; i < BINS / 1024; i++) {
        local[i] = hist[b][t * (BINS / 1024) + i];
        s += local[i];
    }
    int incl = s;
#pragma unroll
    for (int off = 1; off < 32; off <<= 1) {
        int v = __shfl_up_sync(0xffffffffu, incl, off);
        if (lane >= off) incl += v;
    }
    if (lane == 31) wsum[wid] = incl;
    __syncthreads();
    if (t < 32) {
        int v = wsum[t];
        int iw = v;
#pragma unroll
        for (int off = 1; off < 32; off <<= 1) {
            int u = __shfl_up_sync(0xffffffffu, iw, off);
            if (t >= off) iw += u;
        }
        wsum[t] = iw - v;  // exclusive warp offset
    }
    __syncthreads();
    int run = wsum[wid] + (incl - s);
#pragma unroll
    for (int i = 0; i < BINS / 1024; i++) {
        base[b][t * (BINS / 1024) + i] = run;
        run += local[i];
    }
}

// ---------------- sort: scatter ----------------
__global__ void __launch_bounds__(256) scatter_kernel(const float* __restrict__ q) {
    int b = blockIdx.y;
    int n = blockIdx.x * 256 + threadIdx.x;
    int key = g_key[b][n];
    int pos = atomicAdd(&g_base[b][key], 1);
    g_perm[b][pos] = n;
    g_qs[b][0][pos] = q[((size_t)(b * 3 + 0)) * NN + n];
    g_qs[b][1][pos] = q[((size_t)(b * 3 + 1)) * NN + n];
    g_qs[b][2][pos] = q[((size_t)(b * 3 + 2)) * NN + n];
}

__global__ void __launch_bounds__(256) scatter_o_kernel(const float* __restrict__ o) {
    int b = blockIdx.y;
    int m = blockIdx.x * 256 + threadIdx.x;
    int key = g_okey[b][m];
    int pos = atomicAdd(&g_obase[b][key], 1);
    g_operm[b][pos] = m;
    float x = o[((size_t)(b * 3 + 0)) * MM + m];
    float y = o[((size_t)(b * 3 + 1)) * MM + m];
    float z = o[((size_t)(b * 3 + 2)) * MM + m];
    // reference rounding: o2 = (x*x + y*y) + z*z
    float o2 = __fadd_rn(__fadd_rn(__fmul_rn(x, x), __fmul_rn(y, y)), __fmul_rn(z, z));
    g_opts[b][pos] = make_float4(x, y, z, o2);
}

// ---------------- per-subtile AABBs ----------------
__global__ void __launch_bounds__(128) bbox_kernel() {
    int b = blockIdx.y;
    int t = threadIdx.x;  // subtile id 0..127
    int pb = t << 6;
    float4 p = g_opts[b][pb];
    float mnx = p.x, mxx = p.x, mny = p.y, mxy = p.y, mnz = p.z, mxz = p.z;
    for (int j = 1; j < 64; j++) {
        float4 q = g_opts[b][pb + j];
        mnx = fminf(mnx, q.x); mxx = fmaxf(mxx, q.x);
        mny = fminf(mny, q.y); mxy = fmaxf(mxy, q.y);
        mnz = fminf(mnz, q.z); mxz = fmaxf(mxz, q.z);
    }
    g_bbx[b][t][0] = make_float4(mnx, mny, mnz, 0.f);
    g_bbx[b][t][1] = make_float4(mxx, mxy, mxz, 0.f);
}

// ---------------- kernel 1: transpose local_feat (B,64,M) -> (B,M,64) ----------------
__global__ void __launch_bounds__(256) transpose_kernel(const float* __restrict__ lf) {
    __shared__ float tile[64][65];
    int b = blockIdx.y;
    int m0 = blockIdx.x * 64;
    int tid = threadIdx.x;
#pragma unroll
    for (int r = 0; r < 16; r++) {
        int c  = (tid >> 6) + (r << 2);
        int mm = tid & 63;
        tile[c][mm] = lf[((size_t)(b * FEAT + c)) * MM + m0 + mm];
    }
    __syncthreads();
#pragma unroll
    for (int r = 0; r < 16; r++) {
        int mm = (tid >> 6) + (r << 2);
        int c  = tid & 63;
        g_lft[((size_t)(b * MM + m0 + mm)) * FEAT + c] = tile[c][mm];
    }
}

// ---------------- kernel 2: fused KNN, streaming supers + per-lane AABB prune ----------------
__device__ __forceinline__ float dist_key(float qx, float qy, float qz, float q2,
                                          const float4& o) {
    float cross = __fmaf_rn(o.z, qz, __fmaf_rn(o.y, qy, __fmul_rn(o.x, qx)));
    return __fsub_rn(__fadd_rn(q2, o.w), __fmul_rn(2.0f, cross));
}

// Lexicographic (value, original-index) insertion == jax.lax.top_k's stable
// ordering; result independent of point scan order (validated in R7).
__device__ __forceinline__ void topk_insert(float (&d)[KNN], int (&di)[KNN], float sv, int om) {
    if (sv < d[KNN - 1] || (sv == d[KNN - 1] && om < di[KNN - 1])) {
#pragma unroll
        for (int jj = KNN - 1; jj > 0; --jj) {
            bool sh = sv < d[jj - 1] || (sv == d[jj - 1] && om < di[jj - 1]);
            bool he = (sv < d[jj] || (sv == d[jj] && om < di[jj])) && !sh;
            float nd = sh ? d[jj - 1] : (he ? sv : d[jj]);
            int   ni = sh ? di[jj - 1] : (he ? om : di[jj]);
            d[jj] = nd;
            di[jj] = ni;
        }
        if (sv < d[0] || (sv == d[0] && om < di[0])) { d[0] = sv; di[0] = om; }
    }
}

__global__ void __launch_bounds__(128) knn_kernel() {
    __shared__ float4 pts[SUPER];
    __shared__ float4 bbs[NTILE][2];
    int b = blockIdx.y;
    int tid = threadIdx.x;

    for (int i = tid; i < NTILE * 2; i += 128)
        (&bbs[0][0])[i] = (&g_bbx[b][0][0])[i];

    int n = blockIdx.x * 128 + tid;  // sorted query position
    float qx = g_qs[b][0][n];
    float qy = g_qs[b][1][n];
    float qz = g_qs[b][2][n];
    float q2 = __fadd_rn(__fadd_rn(__fmul_rn(qx, qx), __fmul_rn(qy, qy)), __fmul_rn(qz, qz));

    float d[KNN];
    int   di[KNN];
#pragma unroll
    for (int j = 0; j < KNN; j++) { d[j] = 3.0e38f; di[j] = 0x7fffffff; }

    // home mapping: sorted query fraction == sorted point fraction
    int homeg = n >> 6;               // warp-uniform (32 consecutive n, 64-aligned span)
    int homesub = homeg & (SUBS - 1);
    int bsuper = blockIdx.x >> 4;     // block home super-tile (uniform across warps)

    for (int st = 0; st < MM / SUPER; st++) {
        int sp = (bsuper + st) & (MM / SUPER - 1);
        __syncthreads();  // prior super fully consumed
        for (int i = tid; i < SUPER; i += 128) pts[i] = g_opts[b][sp * SUPER + i];
        __syncthreads();

        for (int ss = 0; ss < SUBS; ss++) {
            int sub = (homesub + ss) & (SUBS - 1);
            int gt = sp * SUBS + sub;
            float4 tmn = bbs[gt][0];
            float4 tmx = bbs[gt][1];
            // per-lane min distance from own query to subtile AABB
            float gx = fmaxf(0.f, fmaxf(tmn.x - qx, qx - tmx.x));
            float gy = fmaxf(0.f, fmaxf(tmn.y - qy, qy - tmx.y));
            float gz = fmaxf(0.f, fmaxf(tmn.z - qz, qz - tmx.z));
            float mind2 = fmaf(gx, gx, fmaf(gy, gy, gz * gz));
            if (!__any_sync(0xffffffffu, mind2 <= d[KNN - 1] + 1e-3f)) continue;

            int pb = sub << 6;
            int gbase = sp * SUPER + pb;
            for (int j = 0; j < 64; j += 4) {
                float4 o0 = pts[pb + j + 0];
                float4 o1 = pts[pb + j + 1];
                float4 o2 = pts[pb + j + 2];
                float4 o3 = pts[pb + j + 3];
                int4 om4 = *(const int4*)&g_operm[b][gbase + j];  // uniform LDG.128, L1-hot
                float s0 = dist_key(qx, qy, qz, q2, o0);
                float s1 = dist_key(qx, qy, qz, q2, o1);
                float s2 = dist_key(qx, qy, qz, q2, o2);
                float s3 = dist_key(qx, qy, qz, q2, o3);
                float mn = fminf(fminf(s0, s1), fminf(s2, s3));
                if (__any_sync(0xffffffffu, mn <= d[KNN - 1])) {
                    if (__any_sync(0xffffffffu, s0 <= d[KNN - 1])) topk_insert(d, di, s0, om4.x);
                    if (__any_sync(0xffffffffu, s1 <= d[KNN - 1])) topk_insert(d, di, s1, om4.y);
                    if (__any_sync(0xffffffffu, s2 <= d[KNN - 1])) topk_insert(d, di, s2, om4.z);
                    if (__any_sync(0xffffffffu, s3 <= d[KNN - 1])) topk_insert(d, di, s3, om4.w);
                }
            }
        }
    }

    int orign = g_perm[b][n];
    int outb = ((b * NN) + orign) * KNN;
#pragma unroll
    for (int j = 0; j < KNN; j++) g_knn[outb + j] = di[j];
}

// ---------------- kernel 3: fused MLP + gather + blend (QPB queries/block) ----------------
__global__ void __launch_bounds__(256) mlp_kernel(const float* __restrict__ orig,
                                                  const float* __restrict__ query,
                                                  const float* __restrict__ w2,
                                                  const float* __restrict__ b2,
                                                  float* __restrict__ out) {
    __shared__ float  w1s[FEAT * FEAT];
    __shared__ float  f0s[4][FEAT * K4];
    __shared__ float4 rel4[4][KNN];
    __shared__ int    idxs[4][KNN];
    __shared__ float  red[4][2][8];
    __shared__ float  outs[4][FEAT];

    int tid = threadIdx.x;
    int g = tid >> 6;
    int c = tid & 63;
    int b = blockIdx.y;

    for (int i = tid; i < FEAT * FEAT; i += 256) w1s[i] = g_w1t[i];

    float w00 = g_w0f[c * 3 + 0], w01 = g_w0f[c * 3 + 1], w02 = g_w0f[c * 3 + 2];
    float bb0 = g_b0f[c];
    float bb1 = g_b1f[c];
    float w2a = w2[c], w2b = w2[FEAT + c];
    float b2v = b2[0];

    for (int it = 0; it < QPB / 4; ++it) {
        int n = blockIdx.x * QPB + it * 4 + g;

        if (c < KNN) idxs[g][c] = g_knn[(((size_t)b * NN) + n) * KNN + c];
        __syncthreads();

        float p0 = g_lft[(((size_t)b * MM) + idxs[g][0]) * FEAT + c];
        float p1 = g_lft[(((size_t)b * MM) + idxs[g][1]) * FEAT + c];
        float p2 = g_lft[(((size_t)b * MM) + idxs[g][2]) * FEAT + c];
        float p3 = g_lft[(((size_t)b * MM) + idxs[g][3]) * FEAT + c];

        if (c < 48) {
            int j = c / 3;
            int a = c - j * 3;
            int m = idxs[g][j];
            float qa = query[((size_t)(b * 3 + a)) * NN + n];
            ((float*)&rel4[g][j])[a] = orig[((size_t)(b * 3 + a)) * MM + m] - qa;
        }
        __syncthreads();

        float fg = 0.f;
        float f0k0 = 0.f, f0k1 = 0.f, f0k2 = 0.f, f0k3 = 0.f;
#pragma unroll
        for (int j = 0; j < KNN; j++) {
            float4 r = rel4[g][j];
            float f = fmaf(w00, r.x, fmaf(w01, r.y, fmaf(w02, r.z, bb0)));
            f = fmaxf(f, 0.f);
            fg = fmaxf(fg, f);
            if (j == 0) f0k0 = f;
            if (j == 1) f0k1 = f;
            if (j == 2) f0k2 = f;
            if (j == 3) f0k3 = f;
        }
        *(float4*)&f0s[g][c * 4] = make_float4(f0k0, f0k1, f0k2, f0k3);
        __syncthreads();

        float a0 = bb1, a1 = bb1, a2 = bb1, a3 = bb1;
#pragma unroll 8
        for (int cin = 0; cin < FEAT; ++cin) {
            float wv = w1s[cin * FEAT + c];
            float4 f = *(float4*)&f0s[g][cin * 4];
            a0 = fmaf(wv, f.x, a0);
            a1 = fmaf(wv, f.y, a1);
            a2 = fmaf(wv, f.z, a2);
            a3 = fmaf(wv, f.w, a3);
        }
        float r0 = fmaxf(a0, 0.f), r1 = fmaxf(a1, 0.f), r2 = fmaxf(a2, 0.f), r3 = fmaxf(a3, 0.f);

        float t0 = w2a * r0, t1 = w2a * r1, t2 = w2a * r2, t3 = w2a * r3;
        float u = w2b * fg;
#pragma unroll
        for (int off = 16; off; off >>= 1) {
            t0 += __shfl_down_sync(0xffffffffu, t0, off);
            t1 += __shfl_down_sync(0xffffffffu, t1, off);
            t2 += __shfl_down_sync(0xffffffffu, t2, off);
            t3 += __shfl_down_sync(0xffffffffu, t3, off);
            u  += __shfl_down_sync(0xffffffffu, u, off);
        }
        if ((c & 31) == 0) {
            float* rr = red[g][c >> 5];
            rr[0] = t0; rr[1] = t1; rr[2] = t2; rr[3] = t3; rr[4] = u;
        }
        __syncthreads();

        float base = red[g][0][4] + red[g][1][4] + b2v;
        float z0 = red[g][0][0] + red[g][1][0] + base;
        float z1 = red[g][0][1] + red[g][1][1] + base;
        float z2 = red[g][0][2] + red[g][1][2] + base;
        float z3 = red[g][0][3] + red[g][1][3] + base;
        float wg0 = 1.f / (1.f + expf(-z0));
        float wg1 = 1.f / (1.f + expf(-z1));
        float wg2 = 1.f / (1.f + expf(-z2));
        float wg3 = 1.f / (1.f + expf(-z3));

        float o = (1.f - wg0) * r0 + wg0 * p0;
        o      += (1.f - wg1) * r1 + wg1 * p1;
        o      += (1.f - wg2) * r2 + wg2 * p2;
        o      += (1.f - wg3) * r3 + wg3 * p3;

        outs[g][c] = o;
        __syncthreads();

        int c2 = tid >> 2, g2 = tid & 3;
        out[((size_t)(b * FEAT + c2)) * NN + blockIdx.x * QPB + it * 4 + g2] = outs[g2][c2];
        __syncthreads();
    }
}

// ---------------- launch ----------------
extern "C" void kernel_launch(void* const* d_in, const int* in_sizes, int n_in,
                              void* d_out, int out_size) {
    const float* orig  = (const float*)d_in[0];
    const float* query = (const float*)d_in[1];
    const float* lf    = (const float*)d_in[2];
    const float* w0  = (const float*)d_in[3];
    const float* b0  = (const float*)d_in[4];
    const float* g0  = (const float*)d_in[5];
    const float* be0 = (const float*)d_in[6];
    const float* m0  = (const float*)d_in[7];
    const float* v0  = (const float*)d_in[8];
    const float* w1  = (const float*)d_in[9];
    const float* b1  = (const float*)d_in[10];
    const float* g1  = (const float*)d_in[11];
    const float* be1 = (const float*)d_in[12];
    const float* m1  = (const float*)d_in[13];
    const float* v1  = (const float*)d_in[14];
    const float* w2  = (const float*)d_in[15];
    const float* b2  = (const float*)d_in[16];
    float* out = (float*)d_out;

    fold_kernel<<<8, 256>>>(w0, b0, g0, be0, m0, v0, w1, b1, g1, be1, m1, v1);
    key_kernel<<<dim3(NN / 256, BB), 256>>>(query);
    key_o_kernel<<<dim3(MM / 256, BB), 256>>>(orig);
    scan_kernel<<<dim3(BB, 2), 1024>>>();
    scatter_kernel<<<dim3(NN / 256, BB), 256>>>(query);
    scatter_o_kernel<<<dim3(MM / 256, BB), 256>>>(orig);
    bbox_kernel<<<dim3(1, BB), 128>>>();
    transpose_kernel<<<dim3(MM / 64, BB), 256>>>(lf);
    knn_kernel<<<dim3(NN / 128, BB), 128>>>();
    mlp_kernel<<<dim3(NN / QPB, BB), 256>>>(orig, query, w2, b2, out);
}

// round 10
// speedup vs baseline: 3.3354x; 2.8039x over previous
#include <cuda_runtime.h>
#include <math.h>

#define BB 4
#define NN 8192
#define MM 8192
#define FEAT 64
#define KNN 16
#define K4 4
#define EPS 1e-5f
#define QPB 16     // queries per mlp block
#define BINS 32768 // 15-bit morton (5 bits/dim)
#define NTILE 128  // 64-point subtiles total
#define SUPER 2048 // points per smem stage
#define SUBS 32    // subtiles per super

typedef unsigned long long u64;
typedef unsigned int u32;

// ---------------- scratch (static device globals; no runtime alloc) ----------------
__device__ float g_w0f[FEAT * 3];
__device__ float g_b0f[FEAT];
__device__ float g_w1t[FEAT * FEAT];
__device__ float g_b1f[FEAT];
__device__ int   g_knn[BB * NN * KNN];
__device__ float g_lft[BB * MM * FEAT];   // local_feat transposed to (B, M, FEAT)
// query sort
__device__ int   g_hist[BB][BINS];
__device__ int   g_base[BB][BINS];
__device__ unsigned short g_key[BB][NN];
__device__ int   g_perm[BB][NN];          // sorted pos -> original n
__device__ float g_qs[BB][3][NN];
// point sort
__device__ int   g_ohist[BB][BINS];
__device__ int   g_obase[BB][BINS];
__device__ unsigned short g_okey[BB][MM];
__device__ int   g_operm[BB][MM];         // sorted pos -> original m
__device__ float4 g_opts[BB][MM];         // sorted (x,y,z,o2)
__device__ float4 g_bbx[BB][NTILE][2];    // per-subtile AABB (min,max)

// ---------------- kernel 0: fold BN into conv weights + zero histograms ----------------
__global__ void fold_kernel(const float* __restrict__ w0, const float* __restrict__ b0,
                            const float* __restrict__ g0, const float* __restrict__ be0,
                            const float* __restrict__ m0, const float* __restrict__ v0,
                            const float* __restrict__ w1, const float* __restrict__ b1,
                            const float* __restrict__ g1, const float* __restrict__ be1,
                            const float* __restrict__ m1, const float* __restrict__ v1) {
    int tid = threadIdx.x + blockIdx.x * blockDim.x;
    if (blockIdx.x == 0) {
        if (tid < FEAT) {
            float inv0 = g0[tid] / sqrtf(v0[tid] + EPS);
            g_w0f[tid * 3 + 0] = w0[tid * 3 + 0] * inv0;
            g_w0f[tid * 3 + 1] = w0[tid * 3 + 1] * inv0;
            g_w0f[tid * 3 + 2] = w0[tid * 3 + 2] * inv0;
            g_b0f[tid] = (b0[tid] - m0[tid]) * inv0 + be0[tid];
            float inv1 = g1[tid] / sqrtf(v1[tid] + EPS);
            g_b1f[tid] = (b1[tid] - m1[tid]) * inv1 + be1[tid];
        }
        for (int i = threadIdx.x; i < FEAT * FEAT; i += blockDim.x) {
            int cout = i / FEAT, cin = i % FEAT;
            float inv1 = g1[cout] / sqrtf(v1[cout] + EPS);
            g_w1t[cin * FEAT + cout] = w1[cout * FEAT + cin] * inv1;
        }
    }
    int total = BB * BINS;
    for (int i = tid; i < total; i += blockDim.x * gridDim.x) {
        (&g_hist[0][0])[i] = 0;
        (&g_ohist[0][0])[i] = 0;
    }
}

// ---------------- morton helpers ----------------
__device__ __forceinline__ int spread5(int v) {
    return (v & 1) | ((v & 2) << 2) | ((v & 4) << 4) | ((v & 8) << 6) | ((v & 16) << 8);
}
__device__ __forceinline__ int morton_key(float x, float y, float z) {
    int ux = min(31, max(0, (int)((x + 4.0f) * 4.0f)));
    int uy = min(31, max(0, (int)((y + 4.0f) * 4.0f)));
    int uz = min(31, max(0, (int)((z + 4.0f) * 4.0f)));
    return spread5(ux) | (spread5(uy) << 1) | (spread5(uz) << 2);
}

// ---------------- sort: keys ----------------
__global__ void __launch_bounds__(256) key_kernel(const float* __restrict__ q) {
    int b = blockIdx.y;
    int n = blockIdx.x * 256 + threadIdx.x;
    float x = q[((size_t)(b * 3 + 0)) * NN + n];
    float y = q[((size_t)(b * 3 + 1)) * NN + n];
    float z = q[((size_t)(b * 3 + 2)) * NN + n];
    int key = morton_key(x, y, z);
    g_key[b][n] = (unsigned short)key;
    atomicAdd(&g_hist[b][key], 1);
}

__global__ void __launch_bounds__(256) key_o_kernel(const float* __restrict__ o) {
    int b = blockIdx.y;
    int m = blockIdx.x * 256 + threadIdx.x;
    float x = o[((size_t)(b * 3 + 0)) * MM + m];
    float y = o[((size_t)(b * 3 + 1)) * MM + m];
    float z = o[((size_t)(b * 3 + 2)) * MM + m];
    int key = morton_key(x, y, z);
    g_okey[b][m] = (unsigned short)key;
    atomicAdd(&g_ohist[b][key], 1);
}

// ---------------- sort: two-pass hierarchical scan (no spill; grid (BB,2)) ----------------
__global__ void __launch_bounds__(1024) scan_kernel() {
    __shared__ int wsum[32];
    int b = blockIdx.x;
    int which = blockIdx.y;
    int (*hist)[BINS] = which ? g_ohist : g_hist;
    int (*base)[BINS] = which ? g_obase : g_base;
    int t = threadIdx.x;
    int lane = t & 31;
    int wid = t >> 5;
    int s = 0;
#pragma unroll
    for (int i = 0; i < BINS / 1024; i++) s += hist[b][t * (BINS / 1024) + i];
    int incl = s;
#pragma unroll
    for (int off = 1; off < 32; off <<= 1) {
        int v = __shfl_up_sync(0xffffffffu, incl, off);
        if (lane >= off) incl += v;
    }
    if (lane == 31) wsum[wid] = incl;
    __syncthreads();
    if (t < 32) {
        int v = wsum[t];
        int iw = v;
#pragma unroll
        for (int off = 1; off < 32; off <<= 1) {
            int u = __shfl_up_sync(0xffffffffu, iw, off);
            if (t >= off) iw += u;
        }
        wsum[t] = iw - v;  // exclusive warp offset
    }
    __syncthreads();
    int run = wsum[wid] + (incl - s);
#pragma unroll
    for (int i = 0; i < BINS / 1024; i++) {   // second pass re-reads hist (L2-hot)
        int h = hist[b][t * (BINS / 1024) + i];
        base[b][t * (BINS / 1024) + i] = run;
        run += h;
    }
}

// ---------------- sort: scatter ----------------
__global__ void __launch_bounds__(256) scatter_kernel(const float* __restrict__ q) {
    int b = blockIdx.y;
    int n = blockIdx.x * 256 + threadIdx.x;
    int key = g_key[b][n];
    int pos = atomicAdd(&g_base[b][key], 1);
    g_perm[b][pos] = n;
    g_qs[b][0][pos] = q[((size_t)(b * 3 + 0)) * NN + n];
    g_qs[b][1][pos] = q[((size_t)(b * 3 + 1)) * NN + n];
    g_qs[b][2][pos] = q[((size_t)(b * 3 + 2)) * NN + n];
}

__global__ void __launch_bounds__(256) scatter_o_kernel(const float* __restrict__ o) {
    int b = blockIdx.y;
    int m = blockIdx.x * 256 + threadIdx.x;
    int key = g_okey[b][m];
    int pos = atomicAdd(&g_obase[b][key], 1);
    g_operm[b][pos] = m;
    float x = o[((size_t)(b * 3 + 0)) * MM + m];
    float y = o[((size_t)(b * 3 + 1)) * MM + m];
    float z = o[((size_t)(b * 3 + 2)) * MM + m];
    // reference rounding: o2 = (x*x + y*y) + z*z
    float o2 = __fadd_rn(__fadd_rn(__fmul_rn(x, x), __fmul_rn(y, y)), __fmul_rn(z, z));
    g_opts[b][pos] = make_float4(x, y, z, o2);
}

// ---------------- per-subtile AABBs (one warp per subtile) ----------------
__global__ void __launch_bounds__(128) bbox_kernel() {
    int b = blockIdx.y;
    int t = blockIdx.x * 4 + (threadIdx.x >> 5);  // subtile id
    int lane = threadIdx.x & 31;
    float4 p = g_opts[b][(t << 6) + lane];
    float4 q = g_opts[b][(t << 6) + 32 + lane];
    float mnx = fminf(p.x, q.x), mxx = fmaxf(p.x, q.x);
    float mny = fminf(p.y, q.y), mxy = fmaxf(p.y, q.y);
    float mnz = fminf(p.z, q.z), mxz = fmaxf(p.z, q.z);
#pragma unroll
    for (int off = 16; off; off >>= 1) {
        mnx = fminf(mnx, __shfl_xor_sync(0xffffffffu, mnx, off));
        mxx = fmaxf(mxx, __shfl_xor_sync(0xffffffffu, mxx, off));
        mny = fminf(mny, __shfl_xor_sync(0xffffffffu, mny, off));
        mxy = fmaxf(mxy, __shfl_xor_sync(0xffffffffu, mxy, off));
        mnz = fminf(mnz, __shfl_xor_sync(0xffffffffu, mnz, off));
        mxz = fmaxf(mxz, __shfl_xor_sync(0xffffffffu, mxz, off));
    }
    if (lane == 0) {
        g_bbx[b][t][0] = make_float4(mnx, mny, mnz, 0.f);
        g_bbx[b][t][1] = make_float4(mxx, mxy, mxz, 0.f);
    }
}

// ---------------- kernel 1: transpose local_feat (B,64,M) -> (B,M,64) ----------------
__global__ void __launch_bounds__(256) transpose_kernel(const float* __restrict__ lf) {
    __shared__ float tile[64][65];
    int b = blockIdx.y;
    int m0 = blockIdx.x * 64;
    int tid = threadIdx.x;
#pragma unroll
    for (int r = 0; r < 16; r++) {
        int c  = (tid >> 6) + (r << 2);
        int mm = tid & 63;
        tile[c][mm] = lf[((size_t)(b * FEAT + c)) * MM + m0 + mm];
    }
    __syncthreads();
#pragma unroll
    for (int r = 0; r < 16; r++) {
        int mm = (tid >> 6) + (r << 2);
        int c  = tid & 63;
        g_lft[((size_t)(b * MM + m0 + mm)) * FEAT + c] = tile[c][mm];
    }
}

// ---------------- kernel 2: fused KNN ----------------
__device__ __forceinline__ float dist_key(float qx, float qy, float qz, float q2,
                                          const float4& o) {
    float cross = __fmaf_rn(o.z, qz, __fmaf_rn(o.y, qy, __fmul_rn(o.x, qx)));
    return __fsub_rn(__fadd_rn(q2, o.w), __fmul_rn(2.0f, cross));
}

// float -> order-preserving uint (sign-flip trick), and inverse
__device__ __forceinline__ u32 f2ord(float f) {
    u32 u = __float_as_uint(f);
    return u ^ (u32)(((int)u >> 31) | 0x80000000);
}
__device__ __forceinline__ float ord2f(u32 o) {
    return __uint_as_float(o ^ (u32)(((int)(~o) >> 31) | 0x80000000));
}

// Composed-key (value,index) insertion: ONE u64 comparison per level keeps the
// network a branch-free select chain, while the ordering is exactly
// jax.lax.top_k's stable semantics (asc value, ties -> lowest original index),
// so the result is scan-order invariant. d15f shadows the float value of k[15].
__device__ __forceinline__ void topk_insert(u64 (&k)[KNN], float& d15f, float sv, int om) {
    if (sv <= d15f) {
        u64 kv = ((u64)f2ord(sv) << 32) | (u32)om;
        if (kv < k[KNN - 1]) {
#pragma unroll
            for (int jj = KNN - 1; jj > 0; --jj) {
                bool sh = kv < k[jj - 1];
                bool he = (kv < k[jj]) && !sh;
                k[jj] = sh ? k[jj - 1] : (he ? kv : k[jj]);
            }
            if (kv < k[0]) k[0] = kv;
            d15f = ord2f((u32)(k[KNN - 1] >> 32));
        }
    }
}

__global__ void __launch_bounds__(128) knn_kernel() {
    __shared__ float4 pts[SUPER];
    __shared__ float4 bbs[NTILE][2];
    int b = blockIdx.y;
    int tid = threadIdx.x;

    for (int i = tid; i < NTILE * 2; i += 128)
        (&bbs[0][0])[i] = (&g_bbx[b][0][0])[i];

    int n = blockIdx.x * 128 + tid;  // sorted query position
    float qx = g_qs[b][0][n];
    float qy = g_qs[b][1][n];
    float qz = g_qs[b][2][n];
    float q2 = __fadd_rn(__fadd_rn(__fmul_rn(qx, qx), __fmul_rn(qy, qy)), __fmul_rn(qz, qz));

    // Sentinel: ord-field of 3.0e38f (finite! ord2f round-trips to 3.0e38f so
    // the d15f shadow never becomes NaN), index-field = worst tie rank.
    const u64 SENT = ((u64)0xFFFFFFFFu << 32) | 0xFFFFFFFFu; // placeholder, set below
    u64 k[KNN];
    u64 sent = ((u64)f2ord(3.0e38f) << 32) | 0xFFFFFFFFu;
#pragma unroll
    for (int j = 0; j < KNN; j++) k[j] = sent;
    (void)SENT;
    float d15f = 3.0e38f;

    // home mapping: sorted query fraction == sorted point fraction
    int homesub = (n >> 6) & (SUBS - 1);
    int bsuper = blockIdx.x >> 4;

    for (int st = 0; st < MM / SUPER; st++) {
        int sp = (bsuper + st) & (MM / SUPER - 1);
        __syncthreads();  // prior super consumed (also orders bbs on st==0)
        for (int i = tid; i < SUPER; i += 128) pts[i] = g_opts[b][sp * SUPER + i];
        __syncthreads();

        for (int ss = 0; ss < SUBS; ss++) {
            int sub = (homesub + ss) & (SUBS - 1);
            int gt = sp * SUBS + sub;
            float4 tmn = bbs[gt][0];
            float4 tmx = bbs[gt][1];
            float gx = fmaxf(0.f, fmaxf(tmn.x - qx, qx - tmx.x));
            float gy = fmaxf(0.f, fmaxf(tmn.y - qy, qy - tmx.y));
            float gz = fmaxf(0.f, fmaxf(tmn.z - qz, qz - tmx.z));
            float mind2 = fmaf(gx, gx, fmaf(gy, gy, gz * gz));
            if (!__any_sync(0xffffffffu, mind2 <= d15f + 1e-3f)) continue;  // margin >> rounding slack

            int pb = sub << 6;
            int gbase = sp * SUPER + pb;
            for (int j = 0; j < 64; j += 4) {
                float4 o0 = pts[pb + j + 0];
                float4 o1 = pts[pb + j + 1];
                float4 o2 = pts[pb + j + 2];
                float4 o3 = pts[pb + j + 3];
                float s0 = dist_key(qx, qy, qz, q2, o0);
                float s1 = dist_key(qx, qy, qz, q2, o1);
                float s2 = dist_key(qx, qy, qz, q2, o2);
                float s3 = dist_key(qx, qy, qz, q2, o3);
                float mn = fminf(fminf(s0, s1), fminf(s2, s3));
                if (__any_sync(0xffffffffu, mn <= d15f)) {
                    int4 om4 = *(const int4*)&g_operm[b][gbase + j];  // uniform, L1-hot
                    topk_insert(k, d15f, s0, om4.x);
                    topk_insert(k, d15f, s1, om4.y);
                    topk_insert(k, d15f, s2, om4.z);
                    topk_insert(k, d15f, s3, om4.w);
                }
            }
        }
    }

    int orign = g_perm[b][n];
    int outb = ((b * NN) + orign) * KNN;
#pragma unroll
    for (int j = 0; j < KNN; j++) g_knn[outb + j] = (int)(u32)(k[j] & 0xFFFFFFFFull);
}

// ---------------- kernel 3: fused MLP + gather + blend (QPB queries/block) ----------------
__global__ void __launch_bounds__(256) mlp_kernel(const float* __restrict__ orig,
                                                  const float* __restrict__ query,
                                                  const float* __restrict__ w2,
                                                  const float* __restrict__ b2,
                                                  float* __restrict__ out) {
    __shared__ float  w1s[FEAT * FEAT];
    __shared__ float  f0s[4][FEAT * K4];
    __shared__ float4 rel4[4][KNN];
    __shared__ int    idxs[4][KNN];
    __shared__ float  red[4][2][8];
    __shared__ float  outs[4][FEAT];

    int tid = threadIdx.x;
    int g = tid >> 6;
    int c = tid & 63;
    int b = blockIdx.y;

    for (int i = tid; i < FEAT * FEAT; i += 256) w1s[i] = g_w1t[i];

    float w00 = g_w0f[c * 3 + 0], w01 = g_w0f[c * 3 + 1], w02 = g_w0f[c * 3 + 2];
    float bb0 = g_b0f[c];
    float bb1 = g_b1f[c];
    float w2a = w2[c], w2b = w2[FEAT + c];
    float b2v = b2[0];

    for (int it = 0; it < QPB / 4; ++it) {
        int n = blockIdx.x * QPB + it * 4 + g;

        if (c < KNN) idxs[g][c] = g_knn[(((size_t)b * NN) + n) * KNN + c];
        __syncthreads();

        float p0 = g_lft[(((size_t)b * MM) + idxs[g][0]) * FEAT + c];
        float p1 = g_lft[(((size_t)b * MM) + idxs[g][1]) * FEAT + c];
        float p2 = g_lft[(((size_t)b * MM) + idxs[g][2]) * FEAT + c];
        float p3 = g_lft[(((size_t)b * MM) + idxs[g][3]) * FEAT + c];

        if (c < 48) {
            int j = c / 3;
            int a = c - j * 3;
            int m = idxs[g][j];
            float qa = query[((size_t)(b * 3 + a)) * NN + n];
            ((float*)&rel4[g][j])[a] = orig[((size_t)(b * 3 + a)) * MM + m] - qa;
        }
        __syncthreads();

        float fg = 0.f;
        float f0k0 = 0.f, f0k1 = 0.f, f0k2 = 0.f, f0k3 = 0.f;
#pragma unroll
        for (int j = 0; j < KNN; j++) {
            float4 r = rel4[g][j];
            float f = fmaf(w00, r.x, fmaf(w01, r.y, fmaf(w02, r.z, bb0)));
            f = fmaxf(f, 0.f);
            fg = fmaxf(fg, f);
            if (j == 0) f0k0 = f;
            if (j == 1) f0k1 = f;
            if (j == 2) f0k2 = f;
            if (j == 3) f0k3 = f;
        }
        *(float4*)&f0s[g][c * 4] = make_float4(f0k0, f0k1, f0k2, f0k3);
        __syncthreads();

        float a0 = bb1, a1 = bb1, a2 = bb1, a3 = bb1;
#pragma unroll 8
        for (int cin = 0; cin < FEAT; ++cin) {
            float wv = w1s[cin * FEAT + c];
            float4 f = *(float4*)&f0s[g][cin * 4];
            a0 = fmaf(wv, f.x, a0);
            a1 = fmaf(wv, f.y, a1);
            a2 = fmaf(wv, f.z, a2);
            a3 = fmaf(wv, f.w, a3);
        }
        float r0 = fmaxf(a0, 0.f), r1 = fmaxf(a1, 0.f), r2 = fmaxf(a2, 0.f), r3 = fmaxf(a3, 0.f);

        float t0 = w2a * r0, t1 = w2a * r1, t2 = w2a * r2, t3 = w2a * r3;
        float u = w2b * fg;
#pragma unroll
        for (int off = 16; off; off >>= 1) {
            t0 += __shfl_down_sync(0xffffffffu, t0, off);
            t1 += __shfl_down_sync(0xffffffffu, t1, off);
            t2 += __shfl_down_sync(0xffffffffu, t2, off);
            t3 += __shfl_down_sync(0xffffffffu, t3, off);
            u  += __shfl_down_sync(0xffffffffu, u, off);
        }
        if ((c & 31) == 0) {
            float* rr = red[g][c >> 5];
            rr[0] = t0; rr[1] = t1; rr[2] = t2; rr[3] = t3; rr[4] = u;
        }
        __syncthreads();

        float base = red[g][0][4] + red[g][1][4] + b2v;
        float z0 = red[g][0][0] + red[g][1][0] + base;
        float z1 = red[g][0][1] + red[g][1][1] + base;
        float z2 = red[g][0][2] + red[g][1][2] + base;
        float z3 = red[g][0][3] + red[g][1][3] + base;
        float wg0 = 1.f / (1.f + expf(-z0));
        float wg1 = 1.f / (1.f + expf(-z1));
        float wg2 = 1.f / (1.f + expf(-z2));
        float wg3 = 1.f / (1.f + expf(-z3));

        float o = (1.f - wg0) * r0 + wg0 * p0;
        o      += (1.f - wg1) * r1 + wg1 * p1;
        o      += (1.f - wg2) * r2 + wg2 * p2;
        o      += (1.f - wg3) * r3 + wg3 * p3;

        outs[g][c] = o;
        __syncthreads();

        int c2 = tid >> 2, g2 = tid & 3;
        out[((size_t)(b * FEAT + c2)) * NN + blockIdx.x * QPB + it * 4 + g2] = outs[g2][c2];
        __syncthreads();
    }
}

// ---------------- launch ----------------
extern "C" void kernel_launch(void* const* d_in, const int* in_sizes, int n_in,
                              void* d_out, int out_size) {
    const float* orig  = (const float*)d_in[0];
    const float* query = (const float*)d_in[1];
    const float* lf    = (const float*)d_in[2];
    const float* w0  = (const float*)d_in[3];
    const float* b0  = (const float*)d_in[4];
    const float* g0  = (const float*)d_in[5];
    const float* be0 = (const float*)d_in[6];
    const float* m0  = (const float*)d_in[7];
    const float* v0  = (const float*)d_in[8];
    const float* w1  = (const float*)d_in[9];
    const float* b1  = (const float*)d_in[10];
    const float* g1  = (const float*)d_in[11];
    const float* be1 = (const float*)d_in[12];
    const float* m1  = (const float*)d_in[13];
    const float* v1  = (const float*)d_in[14];
    const float* w2  = (const float*)d_in[15];
    const float* b2  = (const float*)d_in[16];
    float* out = (float*)d_out;

    fold_kernel<<<8, 256>>>(w0, b0, g0, be0, m0, v0, w1, b1, g1, be1, m1, v1);
    key_kernel<<<dim3(NN / 256, BB), 256>>>(query);
    key_o_kernel<<<dim3(MM / 256, BB), 256>>>(orig);
    scan_kernel<<<dim3(BB, 2), 1024>>>();
    scatter_kernel<<<dim3(NN / 256, BB), 256>>>(query);
    scatter_o_kernel<<<dim3(MM / 256, BB), 256>>>(orig);
    bbox_kernel<<<dim3(NTILE / 4, BB), 128>>>();
    transpose_kernel<<<dim3(MM / 64, BB), 256>>>(lf);
    knn_kernel<<<dim3(NN / 128, BB), 128>>>();
    mlp_kernel<<<dim3(NN / QPB, BB), 256>>>(orig, query, w2, b2, out);
}

// round 11
// speedup vs baseline: 4.0246x; 1.2066x over previous
#include <cuda_runtime.h>
#include <math.h>

#define BB 4
#define NN 8192
#define MM 8192
#define FEAT 64
#define KNN 16
#define K4 4
#define EPS 1e-5f
#define QPB 16     // queries per mlp block
#define BINS 4096  // 12-bit morton (4 bits/dim)
#define SUPER 2048 // points per smem stage
#define SUBS 32    // 64-point subtiles per super

typedef unsigned long long u64;
typedef unsigned int u32;

// ---------------- scratch (static device globals; zero-initialized at load) ----------------
__device__ float g_w0f[FEAT * 3];
__device__ float g_b0f[FEAT];
__device__ float g_w1t[FEAT * FEAT];
__device__ float g_b1f[FEAT];
__device__ int   g_knn[BB * NN * KNN];
__device__ float g_lft[BB * MM * FEAT];   // local_feat transposed to (B, M, FEAT)
// sorts (hist is zeroed by scan_kernel after use -> invariant across graph replays)
__device__ int   g_hist[BB][BINS];
__device__ int   g_base[BB][BINS];
__device__ unsigned short g_key[BB][NN];
__device__ int   g_perm[BB][NN];          // sorted pos -> original n
__device__ float g_qs[BB][3][NN];
__device__ int   g_ohist[BB][BINS];
__device__ int   g_obase[BB][BINS];
__device__ unsigned short g_okey[BB][MM];
__device__ int   g_operm[BB][MM];         // sorted pos -> original m
__device__ float4 g_opts[BB][MM];         // sorted (x,y,z,o2)

// ---------------- morton helpers (4 bits/dim) ----------------
__device__ __forceinline__ int spread4(int v) {
    return (v & 1) | ((v & 2) << 2) | ((v & 4) << 4) | ((v & 8) << 6);
}
__device__ __forceinline__ int morton_key(float x, float y, float z) {
    int ux = min(15, max(0, (int)((x + 4.0f) * 2.0f)));
    int uy = min(15, max(0, (int)((y + 4.0f) * 2.0f)));
    int uz = min(15, max(0, (int)((z + 4.0f) * 2.0f)));
    return spread4(ux) | (spread4(uy) << 1) | (spread4(uz) << 2);
}

// ---------------- launch 0: keys for queries AND points ----------------
__global__ void __launch_bounds__(256) keys_kernel(const float* __restrict__ q,
                                                   const float* __restrict__ o) {
    int b = blockIdx.y;
    int n = blockIdx.x * 256 + threadIdx.x;
    float qx = q[((size_t)(b * 3 + 0)) * NN + n];
    float qy = q[((size_t)(b * 3 + 1)) * NN + n];
    float qz = q[((size_t)(b * 3 + 2)) * NN + n];
    int kq = morton_key(qx, qy, qz);
    g_key[b][n] = (unsigned short)kq;
    atomicAdd(&g_hist[b][kq], 1);

    float ox = o[((size_t)(b * 3 + 0)) * MM + n];
    float oy = o[((size_t)(b * 3 + 1)) * MM + n];
    float oz = o[((size_t)(b * 3 + 2)) * MM + n];
    int ko = morton_key(ox, oy, oz);
    g_okey[b][n] = (unsigned short)ko;
    atomicAdd(&g_ohist[b][ko], 1);
}

// ---------------- launch 1: scan both hists, then re-zero them ----------------
__global__ void __launch_bounds__(1024) scan_kernel() {
    __shared__ int wsum[32];
    int b = blockIdx.x;
    int which = blockIdx.y;
    int (*hist)[BINS] = which ? g_ohist : g_hist;
    int (*base)[BINS] = which ? g_obase : g_base;
    int t = threadIdx.x;
    int lane = t & 31;
    int wid = t >> 5;
    int local[BINS / 1024];
    int s = 0;
#pragma unroll
    for (int i = 0; i < BINS / 1024; i++) {
        local[i] = hist[b][t * (BINS / 1024) + i];
        s += local[i];
    }
    int incl = s;
#pragma unroll
    for (int off = 1; off < 32; off <<= 1) {
        int v = __shfl_up_sync(0xffffffffu, incl, off);
        if (lane >= off) incl += v;
    }
    if (lane == 31) wsum[wid] = incl;
    __syncthreads();
    if (t < 32) {
        int v = wsum[t];
        int iw = v;
#pragma unroll
        for (int off = 1; off < 32; off <<= 1) {
            int u = __shfl_up_sync(0xffffffffu, iw, off);
            if (t >= off) iw += u;
        }
        wsum[t] = iw - v;  // exclusive warp offset
    }
    __syncthreads();
    int run = wsum[wid] + (incl - s);
#pragma unroll
    for (int i = 0; i < BINS / 1024; i++) {
        base[b][t * (BINS / 1024) + i] = run;
        run += local[i];
        hist[b][t * (BINS / 1024) + i] = 0;   // ready for next launch (graph replay)
    }
}

// ---------------- launch 2: scatter queries AND points ----------------
__global__ void __launch_bounds__(256) scatters_kernel(const float* __restrict__ q,
                                                       const float* __restrict__ o) {
    int b = blockIdx.y;
    int n = blockIdx.x * 256 + threadIdx.x;

    int kq = g_key[b][n];
    int pq = atomicAdd(&g_base[b][kq], 1);
    g_perm[b][pq] = n;
    g_qs[b][0][pq] = q[((size_t)(b * 3 + 0)) * NN + n];
    g_qs[b][1][pq] = q[((size_t)(b * 3 + 1)) * NN + n];
    g_qs[b][2][pq] = q[((size_t)(b * 3 + 2)) * NN + n];

    int ko = g_okey[b][n];
    int po = atomicAdd(&g_obase[b][ko], 1);
    g_operm[b][po] = n;
    float x = o[((size_t)(b * 3 + 0)) * MM + n];
    float y = o[((size_t)(b * 3 + 1)) * MM + n];
    float z = o[((size_t)(b * 3 + 2)) * MM + n];
    // reference rounding: o2 = (x*x + y*y) + z*z
    float o2 = __fadd_rn(__fadd_rn(__fmul_rn(x, x), __fmul_rn(y, y)), __fmul_rn(z, z));
    g_opts[b][po] = make_float4(x, y, z, o2);
}

// ---------------- launch 3: fused KNN (PROFILED SLOT) ----------------
__device__ __forceinline__ float dist_key(float qx, float qy, float qz, float q2,
                                          const float4& o) {
    float cross = __fmaf_rn(o.z, qz, __fmaf_rn(o.y, qy, __fmul_rn(o.x, qx)));
    return __fsub_rn(__fadd_rn(q2, o.w), __fmul_rn(2.0f, cross));
}
__device__ __forceinline__ u32 f2ord(float f) {
    u32 u = __float_as_uint(f);
    return u ^ (u32)(((int)u >> 31) | 0x80000000);
}
__device__ __forceinline__ float ord2f(u32 o) {
    return __uint_as_float(o ^ (u32)(((int)(~o) >> 31) | 0x80000000));
}

// Composed (value,index) u64 key: one compare/level, branch-free select chain;
// ordering == jax.lax.top_k stable semantics -> scan-order invariant.
__device__ __forceinline__ void topk_insert(u64 (&k)[KNN], float& d15f, float sv, int om) {
    if (sv <= d15f) {
        u64 kv = ((u64)f2ord(sv) << 32) | (u32)om;
        if (kv < k[KNN - 1]) {
#pragma unroll
            for (int jj = KNN - 1; jj > 0; --jj) {
                bool sh = kv < k[jj - 1];
                bool he = (kv < k[jj]) && !sh;
                k[jj] = sh ? k[jj - 1] : (he ? kv : k[jj]);
            }
            if (kv < k[0]) k[0] = kv;
            d15f = ord2f((u32)(k[KNN - 1] >> 32));
        }
    }
}

__global__ void __launch_bounds__(128) knn_kernel() {
    __shared__ float4 pts[SUPER];
    __shared__ int    smop[SUPER];
    __shared__ float4 sbb[SUBS][2];   // current super's subtile AABBs
    int b = blockIdx.y;
    int tid = threadIdx.x;
    int lane = tid & 31;
    int wrp = tid >> 5;

    int n = blockIdx.x * 128 + tid;  // sorted query position
    float qx = g_qs[b][0][n];
    float qy = g_qs[b][1][n];
    float qz = g_qs[b][2][n];
    float q2 = __fadd_rn(__fadd_rn(__fmul_rn(qx, qx), __fmul_rn(qy, qy)), __fmul_rn(qz, qz));

    u64 k[KNN];
    u64 sent = ((u64)f2ord(3.0e38f) << 32) | 0xFFFFFFFFu;  // finite value field: no-NaN shadow
#pragma unroll
    for (int j = 0; j < KNN; j++) k[j] = sent;
    float d15f = 3.0e38f;

    int homesub = (n >> 6) & (SUBS - 1);
    int bsuper = blockIdx.x >> 4;

    for (int st = 0; st < MM / SUPER; st++) {
        int sp = (bsuper + st) & (MM / SUPER - 1);
        __syncthreads();  // prior super fully consumed
        for (int i = tid; i < SUPER; i += 128) {
            pts[i] = g_opts[b][sp * SUPER + i];
            smop[i] = g_operm[b][sp * SUPER + i];
        }
        __syncthreads();
        // compute this super's 32 subtile AABBs (warp w -> subtiles w*8..w*8+7)
        for (int s8 = 0; s8 < 8; s8++) {
            int sub = wrp * 8 + s8;
            float4 p = pts[(sub << 6) + lane];
            float4 q = pts[(sub << 6) + 32 + lane];
            float mnx = fminf(p.x, q.x), mxx = fmaxf(p.x, q.x);
            float mny = fminf(p.y, q.y), mxy = fmaxf(p.y, q.y);
            float mnz = fminf(p.z, q.z), mxz = fmaxf(p.z, q.z);
#pragma unroll
            for (int off = 16; off; off >>= 1) {
                mnx = fminf(mnx, __shfl_xor_sync(0xffffffffu, mnx, off));
                mxx = fmaxf(mxx, __shfl_xor_sync(0xffffffffu, mxx, off));
                mny = fminf(mny, __shfl_xor_sync(0xffffffffu, mny, off));
                mxy = fmaxf(mxy, __shfl_xor_sync(0xffffffffu, mxy, off));
                mnz = fminf(mnz, __shfl_xor_sync(0xffffffffu, mnz, off));
                mxz = fmaxf(mxz, __shfl_xor_sync(0xffffffffu, mxz, off));
            }
            if (lane == 0) {
                sbb[sub][0] = make_float4(mnx, mny, mnz, 0.f);
                sbb[sub][1] = make_float4(mxx, mxy, mxz, 0.f);
            }
        }
        __syncthreads();

        for (int ss = 0; ss < SUBS; ss++) {
            int sub = (homesub + ss) & (SUBS - 1);
            float4 tmn = sbb[sub][0];
            float4 tmx = sbb[sub][1];
            float gx = fmaxf(0.f, fmaxf(tmn.x - qx, qx - tmx.x));
            float gy = fmaxf(0.f, fmaxf(tmn.y - qy, qy - tmx.y));
            float gz = fmaxf(0.f, fmaxf(tmn.z - qz, qz - tmx.z));
            float mind2 = fmaf(gx, gx, fmaf(gy, gy, gz * gz));
            if (!__any_sync(0xffffffffu, mind2 <= d15f + 1e-3f)) continue;  // margin >> rounding slack

            int pb = sub << 6;
            for (int j = 0; j < 64; j += 8) {
                float4 o0 = pts[pb + j + 0];
                float4 o1 = pts[pb + j + 1];
                float4 o2 = pts[pb + j + 2];
                float4 o3 = pts[pb + j + 3];
                float4 o4 = pts[pb + j + 4];
                float4 o5 = pts[pb + j + 5];
                float4 o6 = pts[pb + j + 6];
                float4 o7 = pts[pb + j + 7];
                float s0 = dist_key(qx, qy, qz, q2, o0);
                float s1 = dist_key(qx, qy, qz, q2, o1);
                float s2 = dist_key(qx, qy, qz, q2, o2);
                float s3 = dist_key(qx, qy, qz, q2, o3);
                float s4 = dist_key(qx, qy, qz, q2, o4);
                float s5 = dist_key(qx, qy, qz, q2, o5);
                float s6 = dist_key(qx, qy, qz, q2, o6);
                float s7 = dist_key(qx, qy, qz, q2, o7);
                float mn = fminf(fminf(fminf(s0, s1), fminf(s2, s3)),
                                 fminf(fminf(s4, s5), fminf(s6, s7)));
                if (__any_sync(0xffffffffu, mn <= d15f)) {
                    topk_insert(k, d15f, s0, smop[pb + j + 0]);
                    topk_insert(k, d15f, s1, smop[pb + j + 1]);
                    topk_insert(k, d15f, s2, smop[pb + j + 2]);
                    topk_insert(k, d15f, s3, smop[pb + j + 3]);
                    topk_insert(k, d15f, s4, smop[pb + j + 4]);
                    topk_insert(k, d15f, s5, smop[pb + j + 5]);
                    topk_insert(k, d15f, s6, smop[pb + j + 6]);
                    topk_insert(k, d15f, s7, smop[pb + j + 7]);
                }
            }
        }
    }

    int orign = g_perm[b][n];
    int outb = ((b * NN) + orign) * KNN;
#pragma unroll
    for (int j = 0; j < KNN; j++) g_knn[outb + j] = (int)(u32)(k[j] & 0xFFFFFFFFull);
}

// ---------------- launch 4: fold BN into conv weights ----------------
__global__ void fold_kernel(const float* __restrict__ w0, const float* __restrict__ b0,
                            const float* __restrict__ g0, const float* __restrict__ be0,
                            const float* __restrict__ m0, const float* __restrict__ v0,
                            const float* __restrict__ w1, const float* __restrict__ b1,
                            const float* __restrict__ g1, const float* __restrict__ be1,
                            const float* __restrict__ m1, const float* __restrict__ v1) {
    int tid = threadIdx.x;
    if (tid < FEAT) {
        float inv0 = g0[tid] / sqrtf(v0[tid] + EPS);
        g_w0f[tid * 3 + 0] = w0[tid * 3 + 0] * inv0;
        g_w0f[tid * 3 + 1] = w0[tid * 3 + 1] * inv0;
        g_w0f[tid * 3 + 2] = w0[tid * 3 + 2] * inv0;
        g_b0f[tid] = (b0[tid] - m0[tid]) * inv0 + be0[tid];
        float inv1 = g1[tid] / sqrtf(v1[tid] + EPS);
        g_b1f[tid] = (b1[tid] - m1[tid]) * inv1 + be1[tid];
    }
    for (int i = tid; i < FEAT * FEAT; i += blockDim.x) {
        int cout = i / FEAT, cin = i % FEAT;
        float inv1 = g1[cout] / sqrtf(v1[cout] + EPS);
        g_w1t[cin * FEAT + cout] = w1[cout * FEAT + cin] * inv1;
    }
}

// ---------------- launch 5: transpose local_feat (B,64,M) -> (B,M,64) ----------------
__global__ void __launch_bounds__(256) transpose_kernel(const float* __restrict__ lf) {
    __shared__ float tile[64][65];
    int b = blockIdx.y;
    int m0 = blockIdx.x * 64;
    int tid = threadIdx.x;
#pragma unroll
    for (int r = 0; r < 16; r++) {
        int c  = (tid >> 6) + (r << 2);
        int mm = tid & 63;
        tile[c][mm] = lf[((size_t)(b * FEAT + c)) * MM + m0 + mm];
    }
    __syncthreads();
#pragma unroll
    for (int r = 0; r < 16; r++) {
        int mm = (tid >> 6) + (r << 2);
        int c  = tid & 63;
        g_lft[((size_t)(b * MM + m0 + mm)) * FEAT + c] = tile[c][mm];
    }
}

// ---------------- launch 6: fused MLP + gather + blend ----------------
__global__ void __launch_bounds__(256) mlp_kernel(const float* __restrict__ orig,
                                                  const float* __restrict__ query,
                                                  const float* __restrict__ w2,
                                                  const float* __restrict__ b2,
                                                  float* __restrict__ out) {
    __shared__ float  w1s[FEAT * FEAT];
    __shared__ float  f0s[4][FEAT * K4];
    __shared__ float4 rel4[4][KNN];
    __shared__ int    idxs[4][KNN];
    __shared__ float  red[4][2][8];
    __shared__ float  outs[4][FEAT];

    int tid = threadIdx.x;
    int g = tid >> 6;
    int c = tid & 63;
    int b = blockIdx.y;

    for (int i = tid; i < FEAT * FEAT; i += 256) w1s[i] = g_w1t[i];

    float w00 = g_w0f[c * 3 + 0], w01 = g_w0f[c * 3 + 1], w02 = g_w0f[c * 3 + 2];
    float bb0 = g_b0f[c];
    float bb1 = g_b1f[c];
    float w2a = w2[c], w2b = w2[FEAT + c];
    float b2v = b2[0];

    for (int it = 0; it < QPB / 4; ++it) {
        int n = blockIdx.x * QPB + it * 4 + g;

        if (c < KNN) idxs[g][c] = g_knn[(((size_t)b * NN) + n) * KNN + c];
        __syncthreads();

        float p0 = g_lft[(((size_t)b * MM) + idxs[g][0]) * FEAT + c];
        float p1 = g_lft[(((size_t)b * MM) + idxs[g][1]) * FEAT + c];
        float p2 = g_lft[(((size_t)b * MM) + idxs[g][2]) * FEAT + c];
        float p3 = g_lft[(((size_t)b * MM) + idxs[g][3]) * FEAT + c];

        if (c < 48) {
            int j = c / 3;
            int a = c - j * 3;
            int m = idxs[g][j];
            float qa = query[((size_t)(b * 3 + a)) * NN + n];
            ((float*)&rel4[g][j])[a] = orig[((size_t)(b * 3 + a)) * MM + m] - qa;
        }
        __syncthreads();

        float fg = 0.f;
        float f0k0 = 0.f, f0k1 = 0.f, f0k2 = 0.f, f0k3 = 0.f;
#pragma unroll
        for (int j = 0; j < KNN; j++) {
            float4 r = rel4[g][j];
            float f = fmaf(w00, r.x, fmaf(w01, r.y, fmaf(w02, r.z, bb0)));
            f = fmaxf(f, 0.f);
            fg = fmaxf(fg, f);
            if (j == 0) f0k0 = f;
            if (j == 1) f0k1 = f;
            if (j == 2) f0k2 = f;
            if (j == 3) f0k3 = f;
        }
        *(float4*)&f0s[g][c * 4] = make_float4(f0k0, f0k1, f0k2, f0k3);
        __syncthreads();

        float a0 = bb1, a1 = bb1, a2 = bb1, a3 = bb1;
#pragma unroll 8
        for (int cin = 0; cin < FEAT; ++cin) {
            float wv = w1s[cin * FEAT + c];
            float4 f = *(float4*)&f0s[g][cin * 4];
            a0 = fmaf(wv, f.x, a0);
            a1 = fmaf(wv, f.y, a1);
            a2 = fmaf(wv, f.z, a2);
            a3 = fmaf(wv, f.w, a3);
        }
        float r0 = fmaxf(a0, 0.f), r1 = fmaxf(a1, 0.f), r2 = fmaxf(a2, 0.f), r3 = fmaxf(a3, 0.f);

        float t0 = w2a * r0, t1 = w2a * r1, t2 = w2a * r2, t3 = w2a * r3;
        float u = w2b * fg;
#pragma unroll
        for (int off = 16; off; off >>= 1) {
            t0 += __shfl_down_sync(0xffffffffu, t0, off);
            t1 += __shfl_down_sync(0xffffffffu, t1, off);
            t2 += __shfl_down_sync(0xffffffffu, t2, off);
            t3 += __shfl_down_sync(0xffffffffu, t3, off);
            u  += __shfl_down_sync(0xffffffffu, u, off);
        }
        if ((c & 31) == 0) {
            float* rr = red[g][c >> 5];
            rr[0] = t0; rr[1] = t1; rr[2] = t2; rr[3] = t3; rr[4] = u;
        }
        __syncthreads();

        float base = red[g][0][4] + red[g][1][4] + b2v;
        float z0 = red[g][0][0] + red[g][1][0] + base;
        float z1 = red[g][0][1] + red[g][1][1] + base;
        float z2 = red[g][0][2] + red[g][1][2] + base;
        float z3 = red[g][0][3] + red[g][1][3] + base;
        float wg0 = 1.f / (1.f + expf(-z0));
        float wg1 = 1.f / (1.f + expf(-z1));
        float wg2 = 1.f / (1.f + expf(-z2));
        float wg3 = 1.f / (1.f + expf(-z3));

        float o = (1.f - wg0) * r0 + wg0 * p0;
        o      += (1.f - wg1) * r1 + wg1 * p1;
        o      += (1.f - wg2) * r2 + wg2 * p2;
        o      += (1.f - wg3) * r3 + wg3 * p3;

        outs[g][c] = o;
        __syncthreads();

        int c2 = tid >> 2, g2 = tid & 3;
        out[((size_t)(b * FEAT + c2)) * NN + blockIdx.x * QPB + it * 4 + g2] = outs[g2][c2];
        __syncthreads();
    }
}

// ---------------- launch ----------------
extern "C" void kernel_launch(void* const* d_in, const int* in_sizes, int n_in,
                              void* d_out, int out_size) {
    const float* orig  = (const float*)d_in[0];
    const float* query = (const float*)d_in[1];
    const float* lf    = (const float*)d_in[2];
    const float* w0  = (const float*)d_in[3];
    const float* b0  = (const float*)d_in[4];
    const float* g0  = (const float*)d_in[5];
    const float* be0 = (const float*)d_in[6];
    const float* m0  = (const float*)d_in[7];
    const float* v0  = (const float*)d_in[8];
    const float* w1  = (const float*)d_in[9];
    const float* b1  = (const float*)d_in[10];
    const float* g1  = (const float*)d_in[11];
    const float* be1 = (const float*)d_in[12];
    const float* m1  = (const float*)d_in[13];
    const float* v1  = (const float*)d_in[14];
    const float* w2  = (const float*)d_in[15];
    const float* b2  = (const float*)d_in[16];
    float* out = (float*)d_out;

    keys_kernel<<<dim3(NN / 256, BB), 256>>>(query, orig);          // launch 0
    scan_kernel<<<dim3(BB, 2), 1024>>>();                           // launch 1 (zeros hists after)
    scatters_kernel<<<dim3(NN / 256, BB), 256>>>(query, orig);      // launch 2
    knn_kernel<<<dim3(NN / 128, BB), 128>>>();                      // launch 3  <-- ncu slot
    fold_kernel<<<1, 256>>>(w0, b0, g0, be0, m0, v0, w1, b1, g1, be1, m1, v1);
    transpose_kernel<<<dim3(MM / 64, BB), 256>>>(lf);
    mlp_kernel<<<dim3(NN / QPB, BB), 256>>>(orig, query, w2, b2, out);
}